// round 4
// baseline (speedup 1.0000x reference)
#include <cuda_runtime.h>
#include <cuda_bf16.h>

// Polyphase resample up=3, down=2, F=1023 taps (341 per phase).
// Per phase p (out[j], j = jp + 3k): y_p[k] = sum_q (3*h[p+3q]) * x[c_p + 2k - q]
//   jp = {1,0,2}[p],  c_p = {171,170,171}[p]
//
// f32x2 FMA: 16 outputs/thread as 8 packed accumulators pairing (k+r, k+r+8).
// Pack (x[e], x[e+16]) slides by -1 per tap -> two parity rotating register
// windows. Refills are STAGED one iteration ahead (load->use > 40 issue slots)
// and filter taps prefetched 2 pairs ahead via a single LDS.128 broadcast.

constexpr int NTAP3    = 341;    // taps per phase
constexpr int HSTRIDE  = 342;    // padded (even) per-phase tap stride, 16B align
constexpr int KTILE    = 1024;   // k-values per phase per block
constexpr int NTHREADS = 192;    // 6 warps: 2 per phase
constexpr int R        = 8;      // f32x2 accumulators per thread (16 outputs)
constexpr int WIN      = 2 * KTILE + 340;        // 2388 x-samples per block
constexpr int PXN      = WIN - 16;               // pairs (i, i+16)
constexpr int PXSK     = PXN + (PXN >> 5) + 4;   // skewed pair-array size

typedef unsigned long long ull;

__device__ __forceinline__ int ps(int i) { return i + (i >> 5); }  // pair skew

__device__ __forceinline__ ull ldpx(const float2* __restrict__ px, int i) {
    return *reinterpret_cast<const ull*>(px + ps(i));
}

__device__ __forceinline__ void fma2(ull& d, ull a, ull b) {
    asm("fma.rn.f32x2 %0, %1, %2, %0;" : "+l"(d) : "l"(a), "l"(b));
}

__global__ void __launch_bounds__(NTHREADS, 4)
resample_poly_kernel(const float* __restrict__ x, const float* __restrict__ h,
                     float* __restrict__ out, int N, int ktotal)
{
    __shared__ float2 px[PXSK];             // pre-paired x window
    __shared__ float2 hdup[3 * HSTRIDE];    // duplicated (v,v) taps, padded

    const int tid = threadIdx.x;
    const int K0  = blockIdx.x * KTILE;
    const int ws  = 2 * K0 - 170;           // global x index of window start

    for (int i = tid; i < PXN; i += NTHREADS) {
        int g  = ws + i;
        int g2 = g + 16;
        float lo = (g  >= 0 && g  < N) ? x[g]  : 0.0f;
        float hi = (g2 >= 0 && g2 < N) ? x[g2] : 0.0f;
        px[ps(i)] = make_float2(lo, hi);
    }
    for (int m = tid; m < 3 * NTAP3; m += NTHREADS) {
        int p = m % 3, q = m / 3;
        float v = 3.0f * h[m];
        hdup[p * HSTRIDE + q] = make_float2(v, v);
    }
    __syncthreads();

    const int wid  = tid >> 5;
    const int lane = tid & 31;
    const int p    = wid >> 1;                    // phase 0..2 (2 warps each)
    const int tip  = ((wid & 1) << 5) | lane;     // 0..63 within phase
    const int cp   = (p == 1) ? 170 : 171;
    const int b    = cp + 170 + 32 * tip;         // local base index
    const int jp   = (p == 0) ? 1 : ((p == 1) ? 0 : 2);
    const int kt   = K0 + 16 * tip;               // first k of this thread

    ull acc[R], PA[R], PB[R];
    #pragma unroll
    for (int r = 0; r < R; ++r) acc[r] = 0ull;
    #pragma unroll
    for (int r = 0; r < R; ++r) PA[r] = ldpx(px, b + 2 * r);       // q=0 chain
    #pragma unroll
    for (int r = 0; r < R; ++r) PB[r] = ldpx(px, b - 1 + 2 * r);   // q=1 chain

    const ull* hq = reinterpret_cast<const ull*>(hdup + p * HSTRIDE);

    // Staged refills (data for taps q+2, q+3 of the NEXT install).
    ull sA = ldpx(px, b - 2);
    ull sB = ldpx(px, b - 3);
    // Filter pipeline: current (q,q+1) and next (q+2,q+3).
    ull hA = hq[0], hB = hq[1], hA2 = hq[2], hB2 = hq[3];

    for (int qo = 0; qo < 336; qo += 16) {
        #pragma unroll
        for (int qp = 0; qp < 8; ++qp) {
            const int q = qo + 2 * qp;
            // Prefetch taps (q+4, q+5) in one 16B broadcast (aligned: q even).
            ulonglong2 hv = *reinterpret_cast<const ulonglong2*>(hq + q + 4);

            // Even chain: read the slot being replaced first, install staged
            // pack (for tap q+2), stage the load for tap q+4.
            fma2(acc[7], PA[(7 - qp) & 7], hA);
            PA[(7 - qp) & 7] = sA;
            sA = ldpx(px, b - q - 4);
            #pragma unroll
            for (int r = 0; r < 7; ++r) fma2(acc[r], PA[(r - qp) & 7], hA);

            // Odd chain.
            fma2(acc[7], PB[(7 - qp) & 7], hB);
            PB[(7 - qp) & 7] = sB;
            sB = ldpx(px, b - q - 5);
            #pragma unroll
            for (int r = 0; r < 7; ++r) fma2(acc[r], PB[(r - qp) & 7], hB);

            hA = hA2; hB = hB2; hA2 = hv.x; hB2 = hv.y;
        }
    }
    // Tail taps 336..340 (b >= 340 so all pair indices >= 0).
    #pragma unroll
    for (int q = 336; q < 341; ++q) {
        ull hh = hq[q];
        #pragma unroll
        for (int r = 0; r < R; ++r) {
            ull pxx = ldpx(px, b - q + 2 * r);
            fma2(acc[r], pxx, hh);
        }
    }

    // acc[r] = (y_p[kt+r], y_p[kt+r+8]) -> out[jp + 3k]
    #pragma unroll
    for (int r = 0; r < R; ++r) {
        float lo, hi;
        asm("mov.b64 {%0, %1}, %2;" : "=f"(lo), "=f"(hi) : "l"(acc[r]));
        int klo = kt + r, khi = kt + r + 8;
        if (klo < ktotal) out[jp + 3 * klo] = lo;
        if (khi < ktotal) out[jp + 3 * khi] = hi;
    }
}

extern "C" void kernel_launch(void* const* d_in, const int* in_sizes, int n_in,
                              void* d_out, int out_size) {
    const float* x = (const float*)d_in[0];
    const float* h = (const float*)d_in[n_in - 1];
    float* out     = (float*)d_out;
    int N          = in_sizes[0];
    int ktotal     = (out_size + 2) / 3;
    int blocks     = (ktotal + KTILE - 1) / KTILE;
    resample_poly_kernel<<<blocks, NTHREADS>>>(x, h, out, N, ktotal);
}

// round 5
// speedup vs baseline: 1.2037x; 1.2037x over previous
#include <cuda_runtime.h>
#include <cuda_bf16.h>

// Polyphase resample up=3, down=2, F=1023 taps (341 per phase).
// Per phase p (out[j], j = jp + 3k): y_p[k] = sum_q (3*h[p+3q]) * x[c_p + 2k - q]
//   jp = {1,0,2}[p],  c_p = {171,170,171}[p]
//
// f32x2 FMA: 16 outputs/thread as 8 packed accumulators pairing (k+r, k+r+8).
// Pack (x[e], x[e+16]) slides by -1 per tap -> two parity rotating register
// windows, refilled from a pre-paired smem window (1 LDS.64 each).
// Outputs are staged through shared memory and written as coalesced STG.128
// (the naive out[jp+3k] scatter was 1/3 of all l1tex wavefronts).

constexpr int NTAP3    = 341;    // taps per phase
constexpr int HSTRIDE  = 342;    // padded per-phase tap stride (16B align)
constexpr int KTILE    = 1024;   // k-values per phase per block
constexpr int NTHREADS = 192;    // 6 warps: 2 per phase
constexpr int R        = 8;      // f32x2 accumulators per thread (16 outputs)
constexpr int WIN      = 2 * KTILE + 340;        // 2388 x-samples per block
constexpr int PXN      = WIN - 16;               // pairs (i, i+16)
constexpr int PXSK     = PXN + (PXN >> 5) + 4;   // skewed pair-array size
constexpr int YPITCH   = 1091;   // per-phase pitch of staged outputs (odd)

typedef unsigned long long ull;

__device__ __forceinline__ int ps(int i) { return i + (i >> 5); }  // pair skew

__device__ __forceinline__ ull ldpx(const float2* __restrict__ px, int i) {
    return *reinterpret_cast<const ull*>(px + ps(i));
}

__device__ __forceinline__ void fma2(ull& d, ull a, ull b) {
    asm("fma.rn.f32x2 %0, %1, %2, %0;" : "+l"(d) : "l"(a), "l"(b));
}

__global__ void __launch_bounds__(NTHREADS, 4)
resample_poly_kernel(const float* __restrict__ x, const float* __restrict__ h,
                     float* __restrict__ out, int N, int ktotal, int nout)
{
    __shared__ __align__(16) float2 px[PXSK];           // x window / y staging
    __shared__ __align__(16) float2 hdup[3 * HSTRIDE];  // duplicated taps

    const int tid = threadIdx.x;
    const int K0  = blockIdx.x * KTILE;
    const int ws  = 2 * K0 - 170;        // global x index of window start

    for (int i = tid; i < PXN; i += NTHREADS) {
        int g  = ws + i;
        int g2 = g + 16;
        float lo = (g  >= 0 && g  < N) ? x[g]  : 0.0f;
        float hi = (g2 >= 0 && g2 < N) ? x[g2] : 0.0f;
        px[ps(i)] = make_float2(lo, hi);
    }
    for (int m = tid; m < 3 * NTAP3; m += NTHREADS) {
        int p = m % 3, q = m / 3;
        float v = 3.0f * h[m];
        hdup[p * HSTRIDE + q] = make_float2(v, v);
    }
    __syncthreads();

    const int wid  = tid >> 5;
    const int lane = tid & 31;
    const int p    = wid >> 1;                    // phase 0..2 (2 warps each)
    const int tip  = ((wid & 1) << 5) | lane;     // 0..63 within phase
    const int cp   = (p == 1) ? 170 : 171;
    const int b    = cp + 170 + 32 * tip;         // local base index

    ull acc[R], PA[R], PB[R];
    #pragma unroll
    for (int r = 0; r < R; ++r) acc[r] = 0ull;
    #pragma unroll
    for (int r = 0; r < R; ++r) PA[r] = ldpx(px, b + 2 * r);       // even q
    #pragma unroll
    for (int r = 0; r < R; ++r) PB[r] = ldpx(px, b - 1 + 2 * r);   // odd q

    const ull* hq = reinterpret_cast<const ull*>(hdup + p * HSTRIDE);

    ull hA = hq[0], hB = hq[1], hA2 = hq[2], hB2 = hq[3];

    for (int qo = 0; qo < 336; qo += 16) {
        #pragma unroll
        for (int qp = 0; qp < 8; ++qp) {
            const int q = qo + 2 * qp;
            // Prefetch taps (q+4, q+5): one 16B broadcast.
            ulonglong2 hv = *reinterpret_cast<const ulonglong2*>(hq + q + 4);
            #pragma unroll
            for (int r = 0; r < R; ++r) fma2(acc[r], PA[(r - qp) & 7], hA);
            PA[(7 - qp) & 7] = ldpx(px, b - q - 2);   // refill for tap q+2
            #pragma unroll
            for (int r = 0; r < R; ++r) fma2(acc[r], PB[(r - qp) & 7], hB);
            PB[(7 - qp) & 7] = ldpx(px, b - q - 3);   // refill for tap q+3
            hA = hA2; hB = hB2; hA2 = hv.x; hB2 = hv.y;
        }
    }
    // Tail taps 336..340 (b >= 340 so all pair indices >= 0).
    #pragma unroll
    for (int q = 336; q < 341; ++q) {
        ull hh = hq[q];
        #pragma unroll
        for (int r = 0; r < R; ++r) {
            ull pxx = ldpx(px, b - q + 2 * r);
            fma2(acc[r], pxx, hh);
        }
    }

    // ---- Epilogue: stage y_p[k] in smem, then coalesced STG.128 ----
    __syncthreads();                       // everyone done reading px
    float* ys = reinterpret_cast<float*>(px);   // 3*YPITCH = 3273 floats, fits

    // STS: lane stride in k is 16, skew k>>4 makes word stride 17 (odd) ->
    // conflict-free.
    const int kb = 16 * tip;
    #pragma unroll
    for (int r = 0; r < R; ++r) {
        float lo, hi;
        asm("mov.b64 {%0, %1}, %2;" : "=f"(lo), "=f"(hi) : "l"(acc[r]));
        int k1 = kb + r, k2 = kb + r + 8;
        ys[p * YPITCH + k1 + (k1 >> 4)] = lo;
        ys[p * YPITCH + k2 + (k2 >> 4)] = hi;
    }
    __syncthreads();

    // Each thread writes 16 consecutive outputs (192*16 = 3072 = 3*KTILE).
    // out residue m -> phase {1,0,2}[m], local k = j/3.
    const int j0  = 16 * tid;              // local out index
    const int jg0 = 3 * K0 + j0;           // global out index
    int m  = j0 % 3;
    int kl = j0 / 3;
    #pragma unroll
    for (int v = 0; v < 4; ++v) {
        float o[4];
        #pragma unroll
        for (int w = 0; w < 4; ++w) {
            int pm = (m == 0) ? 1 : ((m == 1) ? 0 : 2);
            o[w] = ys[pm * YPITCH + kl + (kl >> 4)];
            if (++m == 3) { m = 0; ++kl; }
        }
        int jg = jg0 + 4 * v;
        if (jg + 3 < nout) {
            *reinterpret_cast<float4*>(out + jg) =
                make_float4(o[0], o[1], o[2], o[3]);
        } else {
            #pragma unroll
            for (int w = 0; w < 4; ++w)
                if (jg + w < nout) out[jg + w] = o[w];
        }
    }
}

extern "C" void kernel_launch(void* const* d_in, const int* in_sizes, int n_in,
                              void* d_out, int out_size) {
    const float* x = (const float*)d_in[0];
    const float* h = (const float*)d_in[n_in - 1];
    float* out     = (float*)d_out;
    int N          = in_sizes[0];
    int ktotal     = (out_size + 2) / 3;
    int blocks     = (ktotal + KTILE - 1) / KTILE;
    resample_poly_kernel<<<blocks, NTHREADS>>>(x, h, out, N, ktotal, out_size);
}